// round 12
// baseline (speedup 1.0000x reference)
#include <cuda_runtime.h>
#include <cuda_bf16.h>

// LightConv: out[b,t,h*S+s] = sum_k softmax_k(filters[b,t,h*K+k]) * x[b, t+k-PAD, h*S+s] + bias[h*S+s]
// B=8 T=1024 H=8 S=64 K=31 C=512

#define B_ 8
#define T_ 1024
#define H_ 8
#define S_ 64
#define K_ 31
#define C_ 512
#define HK_ (H_ * K_)      // 248
#define PAD_ 15            // K/2
#define TTILE 64           // t rows per CTA
#define RT 8               // t rows per warp (= per thread, 2 channels each)
#define NTHREADS 256       // 8 warps = 8 t-groups; lane = channel pair
#define NGROUPS 8
#define XROWS (TTILE + 2 * PAD_)   // 94
#define DJ 38              // j slots (uniform band, zeros outside)
#define DSTRIDE (DJ * 8)   // 304 u64 per t-group diag block (2432 B)

// xs: 94*64*4 = 24064 B ; diag(u64): 8*304*8 = 19456 B ; total 43520 B
// 5 CTAs/SM: smem 217.6 KB <= 228 KB, regs cap 51 (65536/1280)
#define SMEM_BYTES (XROWS * S_ * 4 + NGROUPS * DSTRIDE * 8)

typedef unsigned long long u64;

__device__ __forceinline__ u64 pack2(float w) {
    u64 d;
    asm("mov.b64 %0, {%1, %1};" : "=l"(d) : "f"(w));
    return d;
}
__device__ __forceinline__ u64 pack2f(float a, float b) {
    u64 d;
    asm("mov.b64 %0, {%1, %2};" : "=l"(d) : "f"(a), "f"(b));
    return d;
}
__device__ __forceinline__ void fma2(u64& a, u64 x, u64 w) {
    asm("fma.rn.f32x2 %0, %1, %2, %3;" : "=l"(a) : "l"(x), "l"(w), "l"(a));
}
__device__ __forceinline__ float2 unpack2(u64 v) {
    float2 f;
    asm("mov.b64 {%0, %1}, %2;" : "=f"(f.x), "=f"(f.y) : "l"(v));
    return f;
}

__global__ __launch_bounds__(NTHREADS, 5) void lightconv_kernel(
    const float* __restrict__ x,
    const float* __restrict__ filters,
    const float* __restrict__ bias,
    float* __restrict__ out)
{
    extern __shared__ float smem[];
    float* xs  = smem;                                         // [XROWS][64]
    u64*   diag = reinterpret_cast<u64*>(smem + XROWS * S_);   // [8 groups][38 j][8 r] {w,w}

    const int t0   = blockIdx.x * TTILE;
    const int h    = blockIdx.y;
    const int b    = blockIdx.z;
    const int tid  = threadIdx.x;
    const int lane = tid & 31;
    const int warp = tid >> 5;

    // ---- load x tile with float4, zero-fill halo ----
    const float4* xbase4 = reinterpret_cast<const float4*>(x + (size_t)b * T_ * C_ + h * S_);
    float4* xs4w = reinterpret_cast<float4*>(xs);
    #pragma unroll 3
    for (int idx = tid; idx < XROWS * 16; idx += NTHREADS) {
        int row  = idx >> 4;
        int col4 = idx & 15;
        int t    = t0 + row - PAD_;
        float4 v = make_float4(0.f, 0.f, 0.f, 0.f);
        if (t >= 0 && t < T_) v = xbase4[(size_t)t * (C_ / 4) + col4];
        xs4w[idx] = v;
    }
    // zero diag (band edges rely on exact zeros)
    #pragma unroll 5
    for (int i = tid; i < NGROUPS * DSTRIDE; i += NTHREADS)
        diag[i] = 0ull;
    __syncthreads();

    // ---- softmax over K=31 taps: warp per t-row, lane = k; 2 rows/iter ----
    // scatter packed {w,w} into diagonal layout:
    //   weight (t-row, tap k) -> diag[row>>3][(k + (row&7)) * 8 + (row&7)]
    const float* fbase = filters + (size_t)b * T_ * HK_ + h * K_;
    #pragma unroll
    for (int base = warp; base < TTILE; base += 16) {
        int rowA = base, rowB = base + 8;
        float fA = -1e30f, fB = -1e30f;
        if (lane < K_) {
            fA = fbase[(size_t)(t0 + rowA) * HK_ + lane];
            fB = fbase[(size_t)(t0 + rowB) * HK_ + lane];
        }
        float mA = fA, mB = fB;
        #pragma unroll
        for (int o = 16; o > 0; o >>= 1) {
            mA = fmaxf(mA, __shfl_xor_sync(0xffffffffu, mA, o));
            mB = fmaxf(mB, __shfl_xor_sync(0xffffffffu, mB, o));
        }
        float eA = (lane < K_) ? __expf(fA - mA) : 0.0f;
        float eB = (lane < K_) ? __expf(fB - mB) : 0.0f;
        float sA = eA, sB = eB;
        #pragma unroll
        for (int o = 16; o > 0; o >>= 1) {
            sA += __shfl_xor_sync(0xffffffffu, sA, o);
            sB += __shfl_xor_sync(0xffffffffu, sB, o);
        }
        if (lane < K_) {
            int rA = rowA & 7, gA = rowA >> 3;
            int rB = rowB & 7, gB = rowB >> 3;
            diag[gA * DSTRIDE + (lane + rA) * 8 + rA] = pack2(eA * (1.0f / sA));
            diag[gB * DSTRIDE + (lane + rB) * 8 + rB] = pack2(eB * (1.0f / sB));
        }
    }
    __syncthreads();

    // ---- main product ----
    // warp = t-group of RT=8 rows; lane = channel pair (f32x2)
    const int tg = warp;
    const int tl = tg * RT;

    const u64* xsg = reinterpret_cast<const u64*>(xs) + lane;   // element row*32 + lane
    const u64* dg  = diag + tg * DSTRIDE;

    // init accumulators with bias
    float2 bv = reinterpret_cast<const float2*>(bias + h * S_)[lane];
    u64 acc[RT];
    #pragma unroll
    for (int r = 0; r < RT; ++r) acc[r] = pack2f(bv.x, bv.y);

    // uniform banded loop: j = 0..37; out-of-band weights are exactly 0.
    // per j: 4x LDS.128 broadcast (8 packed weights) + 1x LDS.64 (x) + 8 fma2
    #pragma unroll
    for (int j = 0; j < DJ; ++j) {
        ulonglong2 w01 = *reinterpret_cast<const ulonglong2*>(dg + j * 8);
        ulonglong2 w23 = *reinterpret_cast<const ulonglong2*>(dg + j * 8 + 2);
        ulonglong2 w45 = *reinterpret_cast<const ulonglong2*>(dg + j * 8 + 4);
        ulonglong2 w67 = *reinterpret_cast<const ulonglong2*>(dg + j * 8 + 6);
        u64 xv = xsg[(tl + j) * 32];
        fma2(acc[0], xv, w01.x);
        fma2(acc[1], xv, w01.y);
        fma2(acc[2], xv, w23.x);
        fma2(acc[3], xv, w23.y);
        fma2(acc[4], xv, w45.x);
        fma2(acc[5], xv, w45.y);
        fma2(acc[6], xv, w67.x);
        fma2(acc[7], xv, w67.y);
    }

    // ---- epilogue: coalesced float2 stores (bias already folded in) ----
    float* obase = out + ((size_t)b * T_ + t0 + tl) * C_ + h * S_;
    #pragma unroll
    for (int r = 0; r < RT; ++r) {
        float2 o = unpack2(acc[r]);
        reinterpret_cast<float2*>(obase + (size_t)r * C_)[lane] = o;
    }
}

extern "C" void kernel_launch(void* const* d_in, const int* in_sizes, int n_in,
                              void* d_out, int out_size)
{
    const float* x       = (const float*)d_in[0];
    const float* filters = (const float*)d_in[1];
    const float* bias    = (const float*)d_in[2];
    float* out           = (float*)d_out;

    cudaFuncSetAttribute(lightconv_kernel,
                         cudaFuncAttributeMaxDynamicSharedMemorySize, SMEM_BYTES);

    dim3 grid(T_ / TTILE, H_, B_);   // (16, 8, 8) = 1024 CTAs, 5 CTAs/SM target
    lightconv_kernel<<<grid, NTHREADS, SMEM_BYTES>>>(x, filters, bias, out);
}

// round 13
// speedup vs baseline: 1.3026x; 1.3026x over previous
#include <cuda_runtime.h>
#include <cuda_bf16.h>

// LightConv: out[b,t,h*S+s] = sum_k softmax_k(filters[b,t,h*K+k]) * x[b, t+k-PAD, h*S+s] + bias[h*S+s]
// B=8 T=1024 H=8 S=64 K=31 C=512

#define B_ 8
#define T_ 1024
#define H_ 8
#define S_ 64
#define K_ 31
#define C_ 512
#define HK_ (H_ * K_)      // 248
#define PAD_ 15            // K/2
#define TTILE 64           // t rows per CTA
#define RT 4               // t rows per thread (x 4 channels)
#define NTHREADS 256       // 16 t-groups x 16 float4 lanes
#define XROWS (TTILE + 2 * PAD_)   // 94
#define XPAD 68            // x row stride in floats (breaks Delta=4-row bank aliasing)
#define WROWF 36           // weight row stride in floats (Delta=4 rows -> bank +16)

// xs: 94*68*4 = 25568 B ; wd: 64*36*4 = 9216 B ; total 34784 B
// 5 CTAs/SM: smem 173.9 KB, regs cap 51 (65536/1280) -> 40 warps
#define SMEM_BYTES (XROWS * XPAD * 4 + TTILE * WROWF * 4)

typedef unsigned long long u64;

__device__ __forceinline__ u64 pack2(float w) {
    u64 d;
    asm("mov.b64 %0, {%1, %1};" : "=l"(d) : "f"(w));
    return d;
}
__device__ __forceinline__ u64 pack2f(float a, float b) {
    u64 d;
    asm("mov.b64 %0, {%1, %2};" : "=l"(d) : "f"(a), "f"(b));
    return d;
}
__device__ __forceinline__ void fma2(u64& a, u64 x, u64 w) {
    asm("fma.rn.f32x2 %0, %1, %2, %3;" : "=l"(a) : "l"(x), "l"(w), "l"(a));
}
__device__ __forceinline__ float2 unpack2(u64 v) {
    float2 f;
    asm("mov.b64 {%0, %1}, %2;" : "=f"(f.x), "=f"(f.y) : "l"(v));
    return f;
}

__global__ __launch_bounds__(NTHREADS, 5) void lightconv_kernel(
    const float* __restrict__ x,
    const float* __restrict__ filters,
    const float* __restrict__ bias,
    float* __restrict__ out)
{
    extern __shared__ float smem[];
    float* xs = smem;                      // [XROWS][XPAD]
    float* wd = smem + XROWS * XPAD;       // t-major: [TTILE][WROWF]

    const int t0   = blockIdx.x * TTILE;
    const int h    = blockIdx.y;
    const int b    = blockIdx.z;
    const int tid  = threadIdx.x;
    const int lane = tid & 31;
    const int warp = tid >> 5;

    // ---- load x tile with float4 into padded rows, zero-fill halo ----
    const float4* xbase4 = reinterpret_cast<const float4*>(x + (size_t)b * T_ * C_ + h * S_);
    float4* xs4w = reinterpret_cast<float4*>(xs);
    #pragma unroll 3
    for (int idx = tid; idx < XROWS * 16; idx += NTHREADS) {
        int row  = idx >> 4;
        int col4 = idx & 15;
        int t    = t0 + row - PAD_;
        float4 v = make_float4(0.f, 0.f, 0.f, 0.f);
        if (t >= 0 && t < T_) v = xbase4[(size_t)t * (C_ / 4) + col4];
        xs4w[row * (XPAD / 4) + col4] = v;
    }

    // ---- softmax over K=31 taps: warp per t-row, lane = k; 2 rows/iter ----
    const float* fbase = filters + (size_t)b * T_ * HK_ + h * K_;
    #pragma unroll
    for (int row = warp; row < TTILE; row += 16) {
        int rowB = row + 8;
        float fA = -1e30f, fB = -1e30f;
        if (lane < K_) {
            fA = fbase[(size_t)(t0 + row)  * HK_ + lane];
            fB = fbase[(size_t)(t0 + rowB) * HK_ + lane];
        }
        float mA = fA, mB = fB;
        #pragma unroll
        for (int o = 16; o > 0; o >>= 1) {
            mA = fmaxf(mA, __shfl_xor_sync(0xffffffffu, mA, o));
            mB = fmaxf(mB, __shfl_xor_sync(0xffffffffu, mB, o));
        }
        float eA = (lane < K_) ? __expf(fA - mA) : 0.0f;
        float eB = (lane < K_) ? __expf(fB - mB) : 0.0f;
        float sA = eA, sB = eB;
        #pragma unroll
        for (int o = 16; o > 0; o >>= 1) {
            sA += __shfl_xor_sync(0xffffffffu, sA, o);
            sB += __shfl_xor_sync(0xffffffffu, sB, o);
        }
        if (lane < K_) {
            wd[row  * WROWF + lane] = eA * (1.0f / sA);
            wd[rowB * WROWF + lane] = eB * (1.0f / sB);
        }
    }
    __syncthreads();

    // ---- main product ----
    // thread = (s4: 4 channels as 2x f32x2) x (tg: RT=4 t rows)
    // warp halves are t-groups tg, tg+1 (Delta=4 rows): x rows differ by
    // 4*XPAD*4 = 1088 B (bank +16), w rows by 4*WROWF*4 = 576 B (bank +16)
    // -> every LDS is a single wavefront.
    const int s4 = tid & 15;
    const int tg = tid >> 4;       // 0..15
    const int tl = tg * RT;

    const ulonglong2* xs2 = reinterpret_cast<const ulonglong2*>(xs) + s4;  // + row*(XPAD/4)
    const float* wrow = wd + tl * WROWF;

    // init accumulators with bias
    float4 bv = reinterpret_cast<const float4*>(bias + h * S_)[s4];
    u64 acc[RT][2];
    #pragma unroll
    for (int r = 0; r < RT; ++r) {
        acc[r][0] = pack2f(bv.x, bv.y);
        acc[r][1] = pack2f(bv.z, bv.w);
    }

    // Region 1: j = 0..3 triangular (scalar weight loads, static guards)
    #pragma unroll
    for (int j = 0; j < RT; ++j) {
        ulonglong2 xv = xs2[(tl + j) * (XPAD / 4)];
        #pragma unroll
        for (int r = 0; r < RT; ++r) {
            if (r <= j) {
                u64 w2 = pack2(wrow[r * WROWF + (j - r)]);
                fma2(acc[r][0], xv.x, w2);
                fma2(acc[r][1], xv.y, w2);
            }
        }
    }

    // Register weight cache: wreg[r] = 4 consecutive taps for row r.
    // Preload chunks current at j=4 for r=1..3 (r=0 reloads at j=4 itself).
    float wreg[RT][4];
    #pragma unroll
    for (int r = 1; r < RT; ++r)
        *reinterpret_cast<float4*>(wreg[r]) =
            *reinterpret_cast<const float4*>(wrow + r * WROWF);   // base 0

    // Region 2: steady state j = 4..30 (uniform, fully unrolled).
    // Per j: reload wreg[j&3] (chunk base j&~3) with one LDS.128.
    #pragma unroll
    for (int j = RT; j <= 30; ++j) {
        const int jj = j & 3;
        const int jb = j & ~3;
        *reinterpret_cast<float4*>(wreg[jj]) =
            *reinterpret_cast<const float4*>(wrow + jj * WROWF + jb);
        ulonglong2 xv = xs2[(tl + j) * (XPAD / 4)];
        #pragma unroll
        for (int r = 0; r < RT; ++r) {
            u64 w2 = pack2(wreg[r][(j - r) & 3]);
            fma2(acc[r][0], xv.x, w2);
            fma2(acc[r][1], xv.y, w2);
        }
    }

    // Region 3: j = 31..33 triangular (scalar weight loads, static guards)
    #pragma unroll
    for (int j = K_; j < K_ + RT - 1; ++j) {
        ulonglong2 xv = xs2[(tl + j) * (XPAD / 4)];
        #pragma unroll
        for (int r = 0; r < RT; ++r) {
            if (j - r < K_) {
                u64 w2 = pack2(wrow[r * WROWF + (j - r)]);
                fma2(acc[r][0], xv.x, w2);
                fma2(acc[r][1], xv.y, w2);
            }
        }
    }

    // ---- epilogue: vectorized store (bias already folded in) ----
    float4* outbase = reinterpret_cast<float4*>(
        out + ((size_t)b * T_ + t0 + tl) * C_ + h * S_) + s4;
    #pragma unroll
    for (int r = 0; r < RT; ++r) {
        float2 lo = unpack2(acc[r][0]);
        float2 hi = unpack2(acc[r][1]);
        float4 o;
        o.x = lo.x;
        o.y = lo.y;
        o.z = hi.x;
        o.w = hi.y;
        outbase[(size_t)r * (C_ / 4)] = o;
    }
}

extern "C" void kernel_launch(void* const* d_in, const int* in_sizes, int n_in,
                              void* d_out, int out_size)
{
    const float* x       = (const float*)d_in[0];
    const float* filters = (const float*)d_in[1];
    const float* bias    = (const float*)d_in[2];
    float* out           = (float*)d_out;

    cudaFuncSetAttribute(lightconv_kernel,
                         cudaFuncAttributeMaxDynamicSharedMemorySize, SMEM_BYTES);

    dim3 grid(T_ / TTILE, H_, B_);   // (16, 8, 8) = 1024 CTAs, 5 CTAs/SM
    lightconv_kernel<<<grid, NTHREADS, SMEM_BYTES>>>(x, filters, bias, out);
}

// round 15
// speedup vs baseline: 1.3244x; 1.0167x over previous
#include <cuda_runtime.h>
#include <cuda_bf16.h>
#include <cstdint>

// LightConv: out[b,t,h*S+s] = sum_k softmax_k(filters[b,t,h*K+k]) * x[b, t+k-PAD, h*S+s] + bias[h*S+s]
// B=8 T=1024 H=8 S=64 K=31 C=512

#define B_ 8
#define T_ 1024
#define H_ 8
#define S_ 64
#define K_ 31
#define C_ 512
#define HK_ (H_ * K_)      // 248
#define PAD_ 15            // K/2
#define TTILE 64           // t rows per CTA
#define RT 4               // t rows per thread (x 4 channels)
#define NTHREADS 256       // 16 t-groups x 16 float4 lanes
#define XROWS (TTILE + 2 * PAD_)   // 94
#define XPAD 68            // x row stride in floats
#define WROWU 34           // u64 weight row stride (272 B, 16B-aligned; Delta4 rows -> +16 banks)

// xs: 94*68*4 = 25568 B ; wd(u64): 64*34*8 = 17408 B ; total 42976 B
// 5 CTAs/SM: smem 214.9 KB <= 228 KB, regs cap 51
#define SMEM_BYTES (XROWS * XPAD * 4 + TTILE * WROWU * 8)

typedef unsigned long long u64;

__device__ __forceinline__ u64 pack2(float w) {
    u64 d;
    asm("mov.b64 %0, {%1, %1};" : "=l"(d) : "f"(w));
    return d;
}
__device__ __forceinline__ u64 pack2f(float a, float b) {
    u64 d;
    asm("mov.b64 %0, {%1, %2};" : "=l"(d) : "f"(a), "f"(b));
    return d;
}
__device__ __forceinline__ void fma2(u64& a, u64 x, u64 w) {
    asm("fma.rn.f32x2 %0, %1, %2, %3;" : "=l"(a) : "l"(x), "l"(w), "l"(a));
}
__device__ __forceinline__ float2 unpack2(u64 v) {
    float2 f;
    asm("mov.b64 {%0, %1}, %2;" : "=f"(f.x), "=f"(f.y) : "l"(v));
    return f;
}
__device__ __forceinline__ void cp_async16(unsigned int smem_addr, const void* gptr, int src_bytes) {
    asm volatile("cp.async.cg.shared.global [%0], [%1], 16, %2;"
                 :: "r"(smem_addr), "l"(gptr), "r"(src_bytes));
}

__global__ __launch_bounds__(NTHREADS, 5) void lightconv_kernel(
    const float* __restrict__ x,
    const float* __restrict__ filters,
    const float* __restrict__ bias,
    float* __restrict__ out)
{
    extern __shared__ float smem[];
    float* xs = smem;                                          // [XROWS][XPAD]
    u64*   wd = reinterpret_cast<u64*>(smem + XROWS * XPAD);   // [TTILE][WROWU] {w,w}

    const int t0   = blockIdx.x * TTILE;
    const int h    = blockIdx.y;
    const int b    = blockIdx.z;
    const int tid  = threadIdx.x;
    const int lane = tid & 31;
    const int warp = tid >> 5;

    // ---- async x tile load (overlapped with softmax below) ----
    const float4* xbase4 = reinterpret_cast<const float4*>(x + (size_t)b * T_ * C_ + h * S_);
    #pragma unroll 3
    for (int idx = tid; idx < XROWS * 16; idx += NTHREADS) {
        int row  = idx >> 4;
        int col4 = idx & 15;
        int t    = t0 + row - PAD_;
        bool ok  = (t >= 0) && (t < T_);
        int tc   = ok ? t : 0;   // clamped valid address; src-size 0 does the zero-fill
        const float4* src = xbase4 + (size_t)tc * (C_ / 4) + col4;
        unsigned int dst =
            (unsigned int)__cvta_generic_to_shared(xs + row * XPAD + col4 * 4);
        cp_async16(dst, src, ok ? 16 : 0);
    }
    asm volatile("cp.async.commit_group;" ::: "memory");

    // ---- softmax over K=31 taps (runs while x streams in) ----
    // warp per t-row, lane = k; 2 rows/iter; store duplicated {w,w}
    const float* fbase = filters + (size_t)b * T_ * HK_ + h * K_;
    #pragma unroll
    for (int row = warp; row < TTILE; row += 16) {
        int rowB = row + 8;
        float fA = -1e30f, fB = -1e30f;
        if (lane < K_) {
            fA = fbase[(size_t)(t0 + row)  * HK_ + lane];
            fB = fbase[(size_t)(t0 + rowB) * HK_ + lane];
        }
        float mA = fA, mB = fB;
        #pragma unroll
        for (int o = 16; o > 0; o >>= 1) {
            mA = fmaxf(mA, __shfl_xor_sync(0xffffffffu, mA, o));
            mB = fmaxf(mB, __shfl_xor_sync(0xffffffffu, mB, o));
        }
        float eA = (lane < K_) ? __expf(fA - mA) : 0.0f;
        float eB = (lane < K_) ? __expf(fB - mB) : 0.0f;
        float sA = eA, sB = eB;
        #pragma unroll
        for (int o = 16; o > 0; o >>= 1) {
            sA += __shfl_xor_sync(0xffffffffu, sA, o);
            sB += __shfl_xor_sync(0xffffffffu, sB, o);
        }
        if (lane < K_) {
            wd[row  * WROWU + lane] = pack2(eA * (1.0f / sA));
            wd[rowB * WROWU + lane] = pack2(eB * (1.0f / sB));
        }
    }
    asm volatile("cp.async.wait_group 0;" ::: "memory");
    __syncthreads();

    // ---- main product ----
    // thread = (s4: 4 channels as 2x f32x2) x (tg: RT=4 t rows)
    // warp halves = t-groups tg, tg+1 (Delta=4 rows): x rows differ by 1088 B
    // (+16 banks), w rows by 1088 B (+16 banks) -> all LDS single-wavefront.
    const int s4 = tid & 15;
    const int tg = tid >> 4;       // 0..15
    const int tl = tg * RT;

    const ulonglong2* xs2 = reinterpret_cast<const ulonglong2*>(xs) + s4;  // + row*(XPAD/4)
    const u64* wrow = wd + tl * WROWU;

    // init accumulators with bias
    float4 bv = reinterpret_cast<const float4*>(bias + h * S_)[s4];
    u64 acc[RT][2];
    #pragma unroll
    for (int r = 0; r < RT; ++r) {
        acc[r][0] = pack2f(bv.x, bv.y);
        acc[r][1] = pack2f(bv.z, bv.w);
    }

    // Region 1: j = 0..3 triangular (scalar u64 weight loads, static guards)
    #pragma unroll
    for (int j = 0; j < RT; ++j) {
        ulonglong2 xv = xs2[(tl + j) * (XPAD / 4)];
        #pragma unroll
        for (int r = 0; r < RT; ++r) {
            if (r <= j) {
                u64 w2 = wrow[r * WROWU + (j - r)];
                fma2(acc[r][0], xv.x, w2);
                fma2(acc[r][1], xv.y, w2);
            }
        }
    }

    // Register weight cache: wreg[r] = ulonglong2 of 2 consecutive {w,w} taps.
    // Preload chunks current at entry j=4: r=1 -> taps{2,3}, r=3 -> taps{0,1}
    // (r=0 and r=2 reload at j=4 itself).
    ulonglong2 wreg[RT];
    wreg[1] = *reinterpret_cast<const ulonglong2*>(wrow + 1 * WROWU + 2);
    wreg[3] = *reinterpret_cast<const ulonglong2*>(wrow + 3 * WROWU + 0);

    // Region 2: steady state j = 4..30 (uniform, fully unrolled).
    // Per j: reload wreg[r] for r in {j&1, (j&1)+2}, chunk base (j-r) [even].
    #pragma unroll
    for (int j = RT; j <= 30; ++j) {
        const int r0 = j & 1;        // reload these two rows' chunks
        const int r1 = r0 + 2;
        wreg[r0] = *reinterpret_cast<const ulonglong2*>(wrow + r0 * WROWU + (j - r0));
        wreg[r1] = *reinterpret_cast<const ulonglong2*>(wrow + r1 * WROWU + (j - r1));
        ulonglong2 xv = xs2[(tl + j) * (XPAD / 4)];
        #pragma unroll
        for (int r = 0; r < RT; ++r) {
            u64 w2 = ((j - r) & 1) ? wreg[r].y : wreg[r].x;
            fma2(acc[r][0], xv.x, w2);
            fma2(acc[r][1], xv.y, w2);
        }
    }

    // Region 3: j = 31..33 triangular (scalar u64 weight loads, static guards)
    #pragma unroll
    for (int j = K_; j < K_ + RT - 1; ++j) {
        ulonglong2 xv = xs2[(tl + j) * (XPAD / 4)];
        #pragma unroll
        for (int r = 0; r < RT; ++r) {
            if (j - r < K_) {
                u64 w2 = wrow[r * WROWU + (j - r)];
                fma2(acc[r][0], xv.x, w2);
                fma2(acc[r][1], xv.y, w2);
            }
        }
    }

    // ---- epilogue: vectorized store (bias already folded in) ----
    float4* outbase = reinterpret_cast<float4*>(
        out + ((size_t)b * T_ + t0 + tl) * C_ + h * S_) + s4;
    #pragma unroll
    for (int r = 0; r < RT; ++r) {
        float2 lo = unpack2(acc[r][0]);
        float2 hi = unpack2(acc[r][1]);
        float4 o;
        o.x = lo.x;
        o.y = lo.y;
        o.z = hi.x;
        o.w = hi.y;
        outbase[(size_t)r * (C_ / 4)] = o;
    }
}

extern "C" void kernel_launch(void* const* d_in, const int* in_sizes, int n_in,
                              void* d_out, int out_size)
{
    const float* x       = (const float*)d_in[0];
    const float* filters = (const float*)d_in[1];
    const float* bias    = (const float*)d_in[2];
    float* out           = (float*)d_out;

    cudaFuncSetAttribute(lightconv_kernel,
                         cudaFuncAttributeMaxDynamicSharedMemorySize, SMEM_BYTES);

    dim3 grid(T_ / TTILE, H_, B_);   // (16, 8, 8) = 1024 CTAs, 5 CTAs/SM
    lightconv_kernel<<<grid, NTHREADS, SMEM_BYTES>>>(x, filters, bias, out);
}